// round 2
// baseline (speedup 1.0000x reference)
#include <cuda_runtime.h>
#include <cuda_bf16.h>
#include <math_constants.h>

#define B 128
#define P 8732
#define C 21
#define NEG_POS_RATIO 3

// ---------------- scratch (no allocations allowed) ----------------
__device__ float g_bg[(size_t)B * P];     // masked bg loss (-inf at positives)
__device__ float g_acc[4];                // 0: pos_conf, 1: reg, 2: mask_sum, 3: neg_conf
__device__ int   g_numpos[B];

// ---------------- helpers ----------------
__device__ __forceinline__ unsigned f2key(float f) {
    unsigned b = __float_as_uint(f);
    return (b & 0x80000000u) ? ~b : (b | 0x80000000u);
}
__device__ __forceinline__ float key2f(unsigned k) {
    unsigned b = (k & 0x80000000u) ? (k & 0x7FFFFFFFu) : ~k;
    return __uint_as_float(b);
}
__device__ __forceinline__ float warp_sum_f(float v) {
    #pragma unroll
    for (int o = 16; o > 0; o >>= 1) v += __shfl_down_sync(0xFFFFFFFFu, v, o);
    return v;
}
__device__ __forceinline__ int warp_sum_i(int v) {
    #pragma unroll
    for (int o = 16; o > 0; o >>= 1) v += __shfl_down_sync(0xFFFFFFFFu, v, o);
    return v;
}

// ---------------- kernel 0: zero accumulators ----------------
__global__ void k_init() {
    int t = threadIdx.x;
    if (t < 4) g_acc[t] = 0.0f;
    if (t < B) g_numpos[t] = 0;
}

// ---------------- kernel 1: streaming pass ----------------
// grid: (ceil(P/128), B), block: 128 threads
__global__ void k_main(const float* __restrict__ conf,
                       const float* __restrict__ pred,
                       const int* __restrict__ labels,
                       const float* __restrict__ gt,
                       const float* __restrict__ mask) {
    __shared__ float sc[128 * C];         // 10.5 KB
    const int b  = blockIdx.y;
    const int p0 = blockIdx.x * 128;
    const int t  = threadIdx.x;
    const int nvalid = min(128, P - p0);

    // coalesced load of confidence tile
    const float* cbase = conf + ((size_t)b * P + p0) * C;
    const int nelem = nvalid * C;
    for (int i = t; i < nelem; i += 128) sc[i] = cbase[i];
    __syncthreads();

    float posc = 0.0f, reg = 0.0f, msum = 0.0f;
    int npos = 0;

    if (t < nvalid) {
        const int p = p0 + t;
        const float* c = sc + t * C;      // 21 stride: conflict-free (gcd(21,32)=1)
        float m = c[0];
        #pragma unroll
        for (int j = 1; j < C; j++) m = fmaxf(m, c[j]);
        float s = 0.0f;
        #pragma unroll
        for (int j = 0; j < C; j++) s += __expf(c[j] - m);
        const float lse = __logf(s) + m;

        const size_t gi = (size_t)b * P + p;
        const int lab = labels[gi];
        const float mk = mask[gi];
        msum = mk;

        const float bg = lse - c[0];
        const bool pos = (lab > 0);
        if (pos) {
            npos = 1;
            posc = mk * (lse - c[lab]);
            const float4 pv = *(const float4*)(pred + gi * 4);
            const float4 gv = *(const float4*)(gt   + gi * 4);
            float r = 0.0f, d, ad;
            d = pv.x - gv.x; ad = fabsf(d); r += (ad < 1.0f) ? 0.5f * d * d : ad - 0.5f;
            d = pv.y - gv.y; ad = fabsf(d); r += (ad < 1.0f) ? 0.5f * d * d : ad - 0.5f;
            d = pv.z - gv.z; ad = fabsf(d); r += (ad < 1.0f) ? 0.5f * d * d : ad - 0.5f;
            d = pv.w - gv.w; ad = fabsf(d); r += (ad < 1.0f) ? 0.5f * d * d : ad - 0.5f;
            reg = mk * r;
        }
        g_bg[gi] = pos ? -CUDART_INF_F : bg;
    }

    // block reduce (4 warps)
    __shared__ float sf[3][4];
    __shared__ int   si[4];
    const int wid = t >> 5, lane = t & 31;
    float a0 = warp_sum_f(posc), a1 = warp_sum_f(reg), a2 = warp_sum_f(msum);
    int   a3 = warp_sum_i(npos);
    if (lane == 0) { sf[0][wid] = a0; sf[1][wid] = a1; sf[2][wid] = a2; si[wid] = a3; }
    __syncthreads();
    if (t == 0) {
        float b0 = sf[0][0] + sf[0][1] + sf[0][2] + sf[0][3];
        float b1 = sf[1][0] + sf[1][1] + sf[1][2] + sf[1][3];
        float b2 = sf[2][0] + sf[2][1] + sf[2][2] + sf[2][3];
        int   b3 = si[0] + si[1] + si[2] + si[3];
        if (b0 != 0.0f) atomicAdd(&g_acc[0], b0);
        if (b1 != 0.0f) atomicAdd(&g_acc[1], b1);
        atomicAdd(&g_acc[2], b2);
        if (b3) atomicAdd(&g_numpos[b], b3);
    }
}

// ---------------- kernel 2: per-row exact top-k sum (radix select) ----------------
// grid: B blocks, 256 threads; 35 keys per thread in registers
#define KPT 35
__global__ void k_select() {
    const int b = blockIdx.x;
    const int t = threadIdx.x;
    const int k = g_numpos[b] * NEG_POS_RATIO;
    if (k <= 0) return;   // uniform across block

    unsigned keys[KPT];
    const float* row = g_bg + (size_t)b * P;
    #pragma unroll
    for (int i = 0; i < KPT; i++) {
        const int idx = i * 256 + t;
        keys[i] = (idx < P) ? f2key(row[idx]) : 0u;
    }

    __shared__ int swarp[8];
    __shared__ int scnt;
    const int wid = t >> 5, lane = t & 31;

    unsigned prefix = 0;
    for (int bit = 31; bit >= 0; bit--) {
        const unsigned cand = prefix | (1u << bit);
        int c = 0;
        #pragma unroll
        for (int i = 0; i < KPT; i++) c += (keys[i] >= cand);
        c = warp_sum_i(c);
        if (lane == 0) swarp[wid] = c;
        __syncthreads();
        if (t == 0) {
            int tot = 0;
            #pragma unroll
            for (int w = 0; w < 8; w++) tot += swarp[w];
            scnt = tot;
        }
        __syncthreads();
        if (scnt >= k) prefix = cand;
        __syncthreads();   // protect swarp/scnt reuse
    }

    // sum of strictly-greater values + (k - count_gt) copies of threshold value
    int cgt = 0; float sgt = 0.0f;
    #pragma unroll
    for (int i = 0; i < KPT; i++) {
        if (keys[i] > prefix) { cgt++; sgt += key2f(keys[i]); }
    }
    cgt = warp_sum_i(cgt);
    sgt = warp_sum_f(sgt);
    __shared__ float swf[8];
    if (lane == 0) { swarp[wid] = cgt; swf[wid] = sgt; }
    __syncthreads();
    if (t == 0) {
        int ctot = 0; float stot = 0.0f;
        #pragma unroll
        for (int w = 0; w < 8; w++) { ctot += swarp[w]; stot += swf[w]; }
        const float tv = (prefix != 0u) ? key2f(prefix) : 0.0f;
        atomicAdd(&g_acc[3], stot + (float)(k - ctot) * tv);
    }
}

// ---------------- kernel 3: finalize ----------------
__global__ void k_final(float* __restrict__ out) {
    const float inv = 1.0f / g_acc[2];
    out[0] = g_acc[1] * inv;
    out[1] = (g_acc[0] + g_acc[3]) * inv;
}

// ---------------- launch ----------------
extern "C" void kernel_launch(void* const* d_in, const int* in_sizes, int n_in,
                              void* d_out, int out_size) {
    const float* conf   = (const float*)d_in[0];
    const float* pred   = (const float*)d_in[1];
    const int*   labels = (const int*)d_in[2];
    const float* gt     = (const float*)d_in[3];
    const float* mask   = (const float*)d_in[4];
    float* out = (float*)d_out;

    k_init<<<1, 128>>>();
    dim3 g1((P + 127) / 128, B);
    k_main<<<g1, 128>>>(conf, pred, labels, gt, mask);
    k_select<<<B, 256>>>();
    k_final<<<1, 1>>>(out);
}

// round 3
// speedup vs baseline: 1.5451x; 1.5451x over previous
#include <cuda_runtime.h>
#include <cuda_bf16.h>
#include <math_constants.h>

#define B 128
#define P 8732
#define C 21
#define NEG_POS_RATIO 3
#define NT 1024
#define KPT 9   // ceil(8732/1024)

__device__ float g_acc[4];   // 0: pos_conf, 1: reg, 2: mask_sum, 3: neg_conf
__device__ int   g_done;

__device__ __forceinline__ unsigned f2key(float f) {
    unsigned b = __float_as_uint(f);
    return (b & 0x80000000u) ? ~b : (b | 0x80000000u);
}
__device__ __forceinline__ float key2f(unsigned k) {
    unsigned b = (k & 0x80000000u) ? (k & 0x7FFFFFFFu) : ~k;
    return __uint_as_float(b);
}
__device__ __forceinline__ float warp_sum_f(float v) {
    #pragma unroll
    for (int o = 16; o > 0; o >>= 1) v += __shfl_down_sync(0xFFFFFFFFu, v, o);
    return v;
}

__global__ __launch_bounds__(NT, 1)
void k_all(const float* __restrict__ conf,
           const float* __restrict__ pred,
           const int*   __restrict__ labels,
           const float* __restrict__ gt,
           const float* __restrict__ mask,
           float* __restrict__ out) {
    const int b    = blockIdx.x;
    const int t    = threadIdx.x;
    const int wid  = t >> 5;
    const int lane = t & 31;

    __shared__ float sredf[4][32];
    __shared__ int   sredi[32];
    __shared__ int   scnt;
    __shared__ int   sk;
    __shared__ bool  sLast;

    // ---------------- phase 1: streaming pass, keys in registers ----------------
    const size_t rb   = (size_t)b * P;
    const float* crow = conf + rb * C;

    unsigned keys[KPT];
    float posc = 0.0f, regl = 0.0f, msum = 0.0f;
    int   npos = 0;

    #pragma unroll
    for (int i = 0; i < KPT; i++) {
        const int idx = t + i * NT;
        unsigned key = 0u;
        if (idx < P) {
            const float* c = crow + (size_t)idx * C;
            float v[C];
            #pragma unroll
            for (int j = 0; j < C; j++) v[j] = __ldg(c + j);

            float m = v[0];
            #pragma unroll
            for (int j = 1; j < C; j++) m = fmaxf(m, v[j]);
            float s = 0.0f;
            #pragma unroll
            for (int j = 0; j < C; j++) s += __expf(v[j] - m);
            const float lse = __logf(s) + m;

            const size_t gi = rb + idx;
            const int   lab = labels[gi];
            const float mk  = mask[gi];
            msum += mk;

            if (lab > 0) {
                npos++;
                float clab = v[0];
                #pragma unroll
                for (int j = 1; j < C; j++) clab = (lab == j) ? v[j] : clab;
                posc += mk * (lse - clab);
                const float4 pv = *(const float4*)(pred + gi * 4);
                const float4 gv = *(const float4*)(gt   + gi * 4);
                float r = 0.0f, d, ad;
                d = pv.x - gv.x; ad = fabsf(d); r += (ad < 1.0f) ? 0.5f * d * d : ad - 0.5f;
                d = pv.y - gv.y; ad = fabsf(d); r += (ad < 1.0f) ? 0.5f * d * d : ad - 0.5f;
                d = pv.z - gv.z; ad = fabsf(d); r += (ad < 1.0f) ? 0.5f * d * d : ad - 0.5f;
                d = pv.w - gv.w; ad = fabsf(d); r += (ad < 1.0f) ? 0.5f * d * d : ad - 0.5f;
                regl += mk * r;
            } else {
                key = f2key(lse - v[0]);   // bg loss >= 0 -> key >= 0x80000000
            }
        }
        keys[i] = key;
    }

    // ---------------- block reduce (posc, regl, msum, npos) ----------------
    posc = warp_sum_f(posc);
    regl = warp_sum_f(regl);
    msum = warp_sum_f(msum);
    npos = __reduce_add_sync(0xFFFFFFFFu, npos);
    if (lane == 0) {
        sredf[0][wid] = posc; sredf[1][wid] = regl; sredf[2][wid] = msum;
        sredi[wid] = npos;
    }
    __syncthreads();
    if (wid == 0) {
        float a0 = sredf[0][lane], a1 = sredf[1][lane], a2 = sredf[2][lane];
        int   a3 = sredi[lane];
        a0 = warp_sum_f(a0); a1 = warp_sum_f(a1); a2 = warp_sum_f(a2);
        a3 = __reduce_add_sync(0xFFFFFFFFu, a3);
        if (lane == 0) {
            atomicAdd(&g_acc[0], a0);
            atomicAdd(&g_acc[1], a1);
            atomicAdd(&g_acc[2], a2);
            sk = a3 * NEG_POS_RATIO;
        }
    }
    __syncthreads();
    const int k = sk;

    // ---------------- phase 2: exact top-k sum via 32-pass radix select ----------------
    float negsum = 0.0f;
    if (k > 0) {
        unsigned prefix = 0u;
        for (int bit = 31; bit >= 0; bit--) {
            const unsigned cand = prefix | (1u << bit);
            int c = 0;
            #pragma unroll
            for (int i = 0; i < KPT; i++) c += (keys[i] >= cand);
            c = __reduce_add_sync(0xFFFFFFFFu, c);
            if (lane == 0) sredi[wid] = c;
            __syncthreads();
            if (wid == 0) {
                int v = __reduce_add_sync(0xFFFFFFFFu, sredi[lane]);
                if (lane == 0) scnt = v;
            }
            __syncthreads();
            if (scnt >= k) prefix = cand;
        }

        // strictly-greater values + ties at threshold
        int cgt = 0; float sgt = 0.0f;
        #pragma unroll
        for (int i = 0; i < KPT; i++) {
            if (keys[i] > prefix) { cgt++; sgt += key2f(keys[i]); }
        }
        cgt = __reduce_add_sync(0xFFFFFFFFu, cgt);
        sgt = warp_sum_f(sgt);
        if (lane == 0) { sredi[wid] = cgt; sredf[0][wid] = sgt; }
        __syncthreads();
        if (t == 0) {
            int ctot = 0; float stot = 0.0f;
            #pragma unroll
            for (int w = 0; w < 32; w++) { ctot += sredi[w]; stot += sredf[0][w]; }
            const float tv = (prefix != 0u) ? key2f(prefix) : 0.0f;
            negsum = stot + (float)(k - ctot) * tv;
        }
    }
    if (t == 0 && negsum != 0.0f) atomicAdd(&g_acc[3], negsum);

    // ---------------- last block finalizes + resets ----------------
    if (t == 0) {
        __threadfence();
        const int prev = atomicAdd(&g_done, 1);
        sLast = (prev == B - 1);
    }
    __syncthreads();
    if (sLast && t == 0) {
        volatile float* a = g_acc;
        const float inv = 1.0f / a[2];
        out[0] = a[1] * inv;
        out[1] = (a[0] + a[3]) * inv;
        a[0] = 0.0f; a[1] = 0.0f; a[2] = 0.0f; a[3] = 0.0f;
        g_done = 0;
    }
}

extern "C" void kernel_launch(void* const* d_in, const int* in_sizes, int n_in,
                              void* d_out, int out_size) {
    const float* conf   = (const float*)d_in[0];
    const float* pred   = (const float*)d_in[1];
    const int*   labels = (const int*)d_in[2];
    const float* gt     = (const float*)d_in[3];
    const float* mask   = (const float*)d_in[4];
    float* out = (float*)d_out;

    k_all<<<B, NT>>>(conf, pred, labels, gt, mask, out);
}

// round 4
// speedup vs baseline: 1.7271x; 1.1178x over previous
#include <cuda_runtime.h>
#include <cuda_bf16.h>
#include <math_constants.h>

#define B 128
#define P 8732
#define C 21
#define NEG_POS_RATIO 3
#define NT 1024
#define NWARP 32
#define KPT 9            // ceil(8732/1024)
#define PC (P * C)       // 183372 floats per row

__device__ float g_acc[4];   // 0: pos_conf, 1: reg, 2: mask_sum, 3: neg_conf
__device__ int   g_done;

__device__ __forceinline__ unsigned f2key(float f) {
    unsigned b = __float_as_uint(f);
    return (b & 0x80000000u) ? ~b : (b | 0x80000000u);
}
__device__ __forceinline__ float key2f(unsigned k) {
    unsigned b = (k & 0x80000000u) ? (k & 0x7FFFFFFFu) : ~k;
    return __uint_as_float(b);
}
__device__ __forceinline__ float warp_sum_f(float v) {
    #pragma unroll
    for (int o = 16; o > 0; o >>= 1) v += __shfl_down_sync(0xFFFFFFFFu, v, o);
    return v;
}

extern __shared__ float s_stage[];   // NWARP * 672 floats = 86016 B

__global__ __launch_bounds__(NT, 1)
void k_all(const float* __restrict__ conf,
           const float* __restrict__ pred,
           const int*   __restrict__ labels,
           const float* __restrict__ gt,
           const float* __restrict__ mask,
           float* __restrict__ out) {
    const int b    = blockIdx.x;
    const int t    = threadIdx.x;
    const int wid  = t >> 5;
    const int lane = t & 31;

    __shared__ float    sredf[2][NWARP];
    __shared__ unsigned sredu[NWARP];
    __shared__ int      sredi[NWARP];
    __shared__ unsigned scnt12;
    __shared__ int      scnt3;
    __shared__ int      sk;
    __shared__ bool     sLast;

    const size_t rb    = (size_t)b * P;
    const float* crow  = conf + rb * C;
    const float4* crow4 = (const float4*)crow;        // row base is 16B aligned
    float*  ws  = s_stage + wid * 672;                // this warp's 32-anchor tile
    float4* ws4 = (float4*)ws;

    unsigned keys[KPT];
    float posc = 0.0f, regl = 0.0f, msum = 0.0f;
    int   npos = 0;

    // ---------------- phase 1: warp-staged streaming ----------------
    #pragma unroll
    for (int i = 0; i < KPT; i++) {
        const int a0 = i * NT + wid * 32;             // warp's anchor base
        const int f0 = a0 * C;                        // float offset (mult of 4)

        __syncwarp();                                 // done reading prev tile
        #pragma unroll
        for (int kk = 0; kk < 6; kk++) {
            const int i4 = lane + kk * 32;            // float4 index in tile
            if (i4 < 168 && (f0 + i4 * 4) < PC)
                ws4[i4] = crow4[(f0 >> 2) + i4];
        }
        __syncwarp();

        const int idx = a0 + lane;
        unsigned key = 0u;
        if (idx < P) {
            const float* c = ws + lane * C;           // stride 21: conflict-free
            float v[C];
            #pragma unroll
            for (int j = 0; j < C; j++) v[j] = c[j];

            float m = v[0];
            #pragma unroll
            for (int j = 1; j < C; j++) m = fmaxf(m, v[j]);
            float s = 0.0f;
            #pragma unroll
            for (int j = 0; j < C; j++) s += __expf(v[j] - m);
            const float lse = __logf(s) + m;

            const size_t gi = rb + idx;
            const int   lab = labels[gi];
            const float mk  = mask[gi];
            msum += mk;

            if (lab > 0) {
                npos++;
                float clab = v[0];
                #pragma unroll
                for (int j = 1; j < C; j++) clab = (lab == j) ? v[j] : clab;
                posc += mk * (lse - clab);
                const float4 pv = *(const float4*)(pred + gi * 4);
                const float4 gv = *(const float4*)(gt   + gi * 4);
                float r = 0.0f, d, ad;
                d = pv.x - gv.x; ad = fabsf(d); r += (ad < 1.0f) ? 0.5f * d * d : ad - 0.5f;
                d = pv.y - gv.y; ad = fabsf(d); r += (ad < 1.0f) ? 0.5f * d * d : ad - 0.5f;
                d = pv.z - gv.z; ad = fabsf(d); r += (ad < 1.0f) ? 0.5f * d * d : ad - 0.5f;
                d = pv.w - gv.w; ad = fabsf(d); r += (ad < 1.0f) ? 0.5f * d * d : ad - 0.5f;
                regl += mk * r;
            } else {
                key = f2key(lse - v[0]);              // bg loss >= 0
            }
        }
        keys[i] = key;
    }

    // ---------------- block reduce scalars ----------------
    posc = warp_sum_f(posc);
    regl = warp_sum_f(regl);
    msum = warp_sum_f(msum);
    npos = __reduce_add_sync(0xFFFFFFFFu, npos);
    if (lane == 0) {
        sredf[0][wid] = posc; sredf[1][wid] = regl; sredu[wid] = __float_as_uint(msum);
        sredi[wid] = npos;
    }
    __syncthreads();
    if (wid == 0) {
        float a0 = sredf[0][lane], a1 = sredf[1][lane], a2 = __uint_as_float(sredu[lane]);
        int   a3 = sredi[lane];
        a0 = warp_sum_f(a0); a1 = warp_sum_f(a1); a2 = warp_sum_f(a2);
        a3 = __reduce_add_sync(0xFFFFFFFFu, a3);
        if (lane == 0) {
            atomicAdd(&g_acc[0], a0);
            atomicAdd(&g_acc[1], a1);
            atomicAdd(&g_acc[2], a2);
            sk = a3 * NEG_POS_RATIO;
        }
    }
    __syncthreads();
    const int k = sk;

    // ---------------- phase 2: exact top-k sum, 2-bit radix (16 passes) ----------------
    float negsum = 0.0f;
    if (k > 0) {
        unsigned prefix = 0u;
        for (int bit = 30; bit >= 0; bit -= 2) {
            const unsigned c1 = prefix | (1u << bit);
            const unsigned c2 = prefix | (2u << bit);
            const unsigned c3 = prefix | (3u << bit);
            unsigned p12 = 0; int n3 = 0;
            #pragma unroll
            for (int i = 0; i < KPT; i++) {
                p12 += (keys[i] >= c1) + ((unsigned)(keys[i] >= c2) << 16);
                n3  += (keys[i] >= c3);
            }
            p12 = __reduce_add_sync(0xFFFFFFFFu, p12);
            n3  = __reduce_add_sync(0xFFFFFFFFu, n3);
            if (lane == 0) { sredu[wid] = p12; sredi[wid] = n3; }
            __syncthreads();
            if (wid == 0) {
                unsigned u = __reduce_add_sync(0xFFFFFFFFu, sredu[lane]);
                int      v = __reduce_add_sync(0xFFFFFFFFu, sredi[lane]);
                if (lane == 0) { scnt12 = u; scnt3 = v; }
            }
            __syncthreads();
            const int n1 = (int)(scnt12 & 0xFFFFu);
            const int n2 = (int)(scnt12 >> 16);
            prefix = (scnt3 >= k) ? c3 : (n2 >= k) ? c2 : (n1 >= k) ? c1 : prefix;
        }

        // strictly-greater values + ties at threshold
        int cgt = 0; float sgt = 0.0f;
        #pragma unroll
        for (int i = 0; i < KPT; i++) {
            if (keys[i] > prefix) { cgt++; sgt += key2f(keys[i]); }
        }
        cgt = __reduce_add_sync(0xFFFFFFFFu, cgt);
        sgt = warp_sum_f(sgt);
        if (lane == 0) { sredi[wid] = cgt; sredf[0][wid] = sgt; }
        __syncthreads();
        if (t == 0) {
            int ctot = 0; float stot = 0.0f;
            #pragma unroll
            for (int w = 0; w < NWARP; w++) { ctot += sredi[w]; stot += sredf[0][w]; }
            const float tv = (prefix != 0u) ? key2f(prefix) : 0.0f;
            negsum = stot + (float)(k - ctot) * tv;
        }
    }
    if (t == 0 && negsum != 0.0f) atomicAdd(&g_acc[3], negsum);

    // ---------------- last block finalizes + resets ----------------
    if (t == 0) {
        __threadfence();
        const int prev = atomicAdd(&g_done, 1);
        sLast = (prev == B - 1);
    }
    __syncthreads();
    if (sLast && t == 0) {
        volatile float* a = g_acc;
        const float inv = 1.0f / a[2];
        out[0] = a[1] * inv;
        out[1] = (a[0] + a[3]) * inv;
        a[0] = 0.0f; a[1] = 0.0f; a[2] = 0.0f; a[3] = 0.0f;
        g_done = 0;
    }
}

extern "C" void kernel_launch(void* const* d_in, const int* in_sizes, int n_in,
                              void* d_out, int out_size) {
    const float* conf   = (const float*)d_in[0];
    const float* pred   = (const float*)d_in[1];
    const int*   labels = (const int*)d_in[2];
    const float* gt     = (const float*)d_in[3];
    const float* mask   = (const float*)d_in[4];
    float* out = (float*)d_out;

    const int smem = NWARP * 672 * sizeof(float);    // 86016 B
    cudaFuncSetAttribute(k_all, cudaFuncAttributeMaxDynamicSharedMemorySize, smem);
    k_all<<<B, NT, smem>>>(conf, pred, labels, gt, mask, out);
}